// round 14
// baseline (speedup 1.0000x reference)
#include <cuda_runtime.h>
#include <cuda_bf16.h>

#define BATCH   4096
#define N_OR    21
#define N_ORN   42
#define N_LN    56
#define N_PN    42
#define N_KC    2000
#define N_ODOR  34
#define NSTEPS  20
#define ALPHA   0.9f
#define VTH     1.0f
#define GSOMA   0.3f
#define ISCALE  0.5f

// ---- packed f32x2 helpers: ONLY fma.rn.f32x2 (the verified pattern) ----
static __device__ __forceinline__ unsigned long long pk2(float lo, float hi) {
    return (unsigned long long)__float_as_uint(lo)
         | ((unsigned long long)__float_as_uint(hi) << 32);
}
static __device__ __forceinline__ float lo2(unsigned long long v) {
    return __uint_as_float((unsigned)v);
}
static __device__ __forceinline__ float hi2(unsigned long long v) {
    return __uint_as_float((unsigned)(v >> 32));
}
static __device__ __forceinline__ unsigned long long fma2(
    unsigned long long a, unsigned long long b, unsigned long long c) {
    unsigned long long r;
    asm("fma.rn.f32x2 %0,%1,%2,%3;" : "=l"(r) : "l"(a), "l"(b), "l"(c));
    return r;
}
#define ONE2  0x3F8000003F800000ull   /* {1.0f,1.0f} */
#define ZERO2 0x0000000000000000ull

// spread 21-bit value to even bit positions of a 64-bit word
__device__ __forceinline__ unsigned long long spread21(unsigned x) {
    unsigned long long v = x & 0x1FFFFFu;
    v = (v | (v << 16)) & 0x0000FFFF0000FFFFull;
    v = (v | (v << 8))  & 0x00FF00FF00FF00FFull;
    v = (v | (v << 4))  & 0x0F0F0F0F0F0F0F0Full;
    v = (v | (v << 2))  & 0x3333333333333333ull;
    v = (v | (v << 1))  & 0x5555555555555555ull;
    return v;
}

// Shared-memory overlay: k1 weight tiles (phase 1) are dead after the mask
// phase; the epilogue's compaction/decode arrays reuse the same bytes.
struct PhaseMask {                    // phase 1 (ORN/LN/PN sim)
    float2 sOLp[N_OR][32];            // pair-summed orn_to_ln rows (28 used)
    float2 sOPp[N_OR][32];            // pair-summed orn_to_pn rows (21 used)
    float2 sLP[N_LN][32];             // ln_to_pn rows (21 used)
    float2 sLPsum[32];                // column sums of ln_to_pn
    float  sSg[32];                   // softplus(or_gains)
};
struct PhaseEpi {                     // phase 3 (compaction + decode)
    int   sIdx[2048];
    float sRate[2048];
    float sLg[8][N_ODOR];
};

// ---------------------------------------------------------------------------
// Fused kernel: one CTA per batch row.
//   Phase 0: all warps cooperatively load k1 tiles into smem.
//   Phase 1: warp 0 runs the 20-step ORN/LN/PN sim for this row, writes the
//            PN mask words to smem. Other warps load APL constants and wait.
//   Phase 2: lanes 0-31 decode mask words -> per-step weight-row offsets.
//   Phase 3: 20-step KC/APL loop (packed f32x2, prefetch-before-barrier),
//            then compaction + warp-sliced decode (overlayed smem).
// Summation orders are identical to the round-12 passing kernel.
// ---------------------------------------------------------------------------
__global__ __launch_bounds__(256, 4) void fused_kernel(
    const float* __restrict__ or_input, const float* __restrict__ or_gains,
    const float* __restrict__ orn_to_pn, const float* __restrict__ orn_to_ln,
    const float* __restrict__ ln_to_pn,
    const float* __restrict__ pn_to_kc, const float* __restrict__ kc_to_apl,
    const float* __restrict__ apl_to_kc, const float* __restrict__ dec_w,
    const float* __restrict__ dec_b, float* __restrict__ out)
{
    __shared__ __align__(16) unsigned char bufA[
        sizeof(PhaseMask) > sizeof(PhaseEpi) ? sizeof(PhaseMask)
                                             : sizeof(PhaseEpi)];
    __shared__ unsigned long long sMaskW[NSTEPS];
    __shared__ int   sCnt[NSTEPS + 1];
    __shared__ int   sOff[NSTEPS + 1][N_PN];
    __shared__ float sW[2][8];
    __shared__ int   sT0;
    __shared__ int   sWTot[8];

    PhaseMask* A = (PhaseMask*)bufA;
    PhaseEpi*  E = (PhaseEpi*)bufA;

    int tid = threadIdx.x;
    int lane = tid & 31, wid = tid >> 5;
    int row = blockIdx.x;

    // ---- phase 0: load k1 tiles (all 256 threads) ----
    for (int i = tid; i < N_OR * 32; i += 256) {
        int p = i >> 5, c = i & 31;
        float2 a = make_float2(0.f, 0.f), b = make_float2(0.f, 0.f);
        if (c < 28) {
            float2 r0 = ((const float2*)(orn_to_ln + (2 * p)     * N_LN))[c];
            float2 r1 = ((const float2*)(orn_to_ln + (2 * p + 1) * N_LN))[c];
            a = make_float2(r0.x + r1.x, r0.y + r1.y);
        }
        if (c < 21) {
            float2 r0 = ((const float2*)(orn_to_pn + (2 * p)     * N_PN))[c];
            float2 r1 = ((const float2*)(orn_to_pn + (2 * p + 1) * N_PN))[c];
            b = make_float2(r0.x + r1.x, r0.y + r1.y);
        }
        A->sOLp[p][c] = a;
        A->sOPp[p][c] = b;
    }
    for (int i = tid; i < N_LN * 32; i += 256) {
        int r = i >> 5, c = i & 31;
        A->sLP[r][c] = (c < 21) ? ((const float2*)(ln_to_pn + r * N_PN))[c]
                                : make_float2(0.f, 0.f);
    }
    if (tid < N_OR) A->sSg[tid] = log1pf(expf(or_gains[tid]));  // softplus
    if (tid < 8) { sW[0][tid] = 0.f; sW[1][tid] = 0.f; }
    __syncthreads();
    if (tid < 32) {
        float sx = 0.f, sy = 0.f;
        for (int r = 0; r < N_LN; r++) {
            sx += A->sLP[r][tid].x; sy += A->sLP[r][tid].y;
        }
        A->sLPsum[tid] = make_float2(sx, sy);
    }
    __syncthreads();

    // ---- k2 per-thread constants (all warps, incl. warp 0 after its sim) ----
    int c0 = tid * 8;
    bool valid = (c0 < N_KC);
    const char* wbase = (const char*)(pn_to_kc + (valid ? c0 : 0));
    const float* aplkp = apl_to_kc + (valid ? c0 : 0);
    const float* aplwp = kc_to_apl + (valid ? c0 : 0);

    unsigned long long aplk0 = 0, aplk1 = 0, aplk2 = 0, aplk3 = 0;
    float aplw[8];
    if (valid) {
        aplk0 = pk2(aplkp[0], aplkp[1]);
        aplk1 = pk2(aplkp[2], aplkp[3]);
        aplk2 = pk2(aplkp[4], aplkp[5]);
        aplk3 = pk2(aplkp[6], aplkp[7]);
        #pragma unroll
        for (int j = 0; j < 8; j++) aplw[j] = aplwp[j];
    } else {
        #pragma unroll
        for (int j = 0; j < 8; j++) aplw[j] = 0.f;
    }

    // ---- phase 1: warp 0 runs the ORN/LN/PN sim for this row ----
    if (wid == 0) {
        float d = (lane < N_OR)
                ? or_input[row * N_OR + lane] * A->sSg[lane] * ISCALE : 0.f;

        float vO = 0.f, vLx = 0.f, vLy = 0.f, vPx = 0.f, vPy = 0.f;

        for (int t = 0; t < NSTEPS; t++) {
            // ORN LIF (one state per OR pair)
            vO = ALPHA * vO + d;
            bool sO = (vO - VTH) > 0.f;
            unsigned bO = __ballot_sync(0xFFFFFFFFu, sO) & 0x1FFFFFu;
            if (sO) vO = 0.f;

            // merged LN drive + PN excitation over OR-pair spikes
            float aLx = 0.f, aLy = 0.f, eEx = 0.f, eEy = 0.f;
            unsigned m = bO;
            while (m) {
                int p = __ffs(m) - 1; m &= m - 1;
                float2 a = A->sOLp[p][lane];
                float2 e = A->sOPp[p][lane];
                aLx += a.x; aLy += a.y; eEx += e.x; eEy += e.y;
            }

            // LN LIF
            vLx = ALPHA * vLx + aLx;
            vLy = ALPHA * vLy + aLy;
            bool sx = (vLx - VTH) > 0.f, sy = (vLy - VTH) > 0.f;
            unsigned bLx = __ballot_sync(0xFFFFFFFFu, sx) & 0x0FFFFFFFu;
            unsigned bLy = __ballot_sync(0xFFFFFFFFu, sy) & 0x0FFFFFFFu;
            if (sx) vLx = 0.f;
            if (sy) vLy = 0.f;

            // LN->PN inhibition: direct or complement (uniform branch)
            float iIx, iIy;
            int nb = __popc(bLx) + __popc(bLy);
            if (nb > 28) {
                iIx = A->sLPsum[lane].x; iIy = A->sLPsum[lane].y;
                m = ~bLx & 0x0FFFFFFFu;
                while (m) {
                    int p = __ffs(m) - 1; m &= m - 1;
                    float2 w = A->sLP[2 * p][lane];
                    iIx -= w.x; iIy -= w.y;
                }
                m = ~bLy & 0x0FFFFFFFu;
                while (m) {
                    int p = __ffs(m) - 1; m &= m - 1;
                    float2 w = A->sLP[2 * p + 1][lane];
                    iIx -= w.x; iIy -= w.y;
                }
            } else {
                iIx = 0.f; iIy = 0.f;
                m = bLx;
                while (m) {
                    int p = __ffs(m) - 1; m &= m - 1;
                    float2 w = A->sLP[2 * p][lane];
                    iIx += w.x; iIy += w.y;
                }
                m = bLy;
                while (m) {
                    int p = __ffs(m) - 1; m &= m - 1;
                    float2 w = A->sLP[2 * p + 1][lane];
                    iIx += w.x; iIy += w.y;
                }
            }

            // PN LIF
            vPx = ALPHA * vPx + eEx - iIx;
            vPy = ALPHA * vPy + eEy - iIy;
            sx = (vPx - VTH) > 0.f; sy = (vPy - VTH) > 0.f;
            unsigned bPx = __ballot_sync(0xFFFFFFFFu, sx) & 0x1FFFFFu;
            unsigned bPy = __ballot_sync(0xFFFFFFFFu, sy) & 0x1FFFFFu;
            if (sx) vPx = 0.f;
            if (sy) vPy = 0.f;

            if (lane == 0)
                sMaskW[t] = spread21(bPx) | (spread21(bPy) << 1);
        }
    }
    __syncthreads();

    // ---- phase 2: decode mask words -> per-step row offsets (lanes 0-31) ----
    if (tid < 32) {
        int n = 0;
        if (tid < NSTEPS) {
            unsigned long long m = sMaskW[tid];
            while (m) {
                int k = __ffsll((long long)m) - 1; m &= m - 1;
                sOff[tid][n++] = k * (N_KC * 4);   // byte offset of weight row
            }
            sCnt[tid] = n;
        }
        if (tid == NSTEPS) sCnt[NSTEPS] = 0;
        unsigned nz = __ballot_sync(0xFFFFFFFFu, n > 0);
        if (tid == 0) sT0 = nz ? (__ffs(nz) - 1) : NSTEPS;
    }
    __syncthreads();

    int t0 = sT0;
    if (t0 >= NSTEPS) {   // no PN spikes ever -> logits = dec_b (CTA-uniform)
        if (tid < N_ODOR) out[(size_t)row * N_ODOR + tid] = dec_b[tid];
        return;
    }

    unsigned long long vd0 = 0, vd1 = 0, vd2 = 0, vd3 = 0;
    unsigned long long va0 = 0, va1 = 0, va2 = 0, va3 = 0;
    int cnt[8];
    #pragma unroll
    for (int j = 0; j < 8; j++) cnt[j] = 0;

    const unsigned long long ALPHA2 = pk2(ALPHA, ALPHA);
    const unsigned long long AG2    = pk2(ALPHA - GSOMA, ALPHA - GSOMA);
    const unsigned long long G2     = pk2(GSOMA, GSOMA);

    // prefetch step t0 rows into vd (state is exactly zero before t0)
    if (valid) {
        int n = sCnt[t0];
        for (int i = 0; i < n; i++) {
            int off = sOff[t0][i];
            float4 a = __ldg((const float4*)(wbase + off));
            float4 b = __ldg((const float4*)(wbase + off + 16));
            vd0 = fma2(ONE2, pk2(a.x, a.y), vd0);
            vd1 = fma2(ONE2, pk2(a.z, a.w), vd1);
            vd2 = fma2(ONE2, pk2(b.x, b.y), vd2);
            vd3 = fma2(ONE2, pk2(b.z, b.w), vd3);
        }
    }

    for (int t = t0; t < NSTEPS; t++) {
        // APL from previous step (buffer (t+1)&1, zero at t0): fixed-order sum
        const float* wprev = sW[(t + 1) & 1];
        float apl = ((((((wprev[0] + wprev[1]) + wprev[2]) + wprev[3])
                     + wprev[4]) + wprev[5]) + wprev[6]) + wprev[7];

        // vd -= apl * aplk  (apl==0 is an exact no-op)
        unsigned long long napl2 = pk2(-apl, -apl);
        vd0 = fma2(napl2, aplk0, vd0);
        vd1 = fma2(napl2, aplk1, vd1);
        vd2 = fma2(napl2, aplk2, vd2);
        vd3 = fma2(napl2, aplk3, vd3);

        // axon compartment: va = (ALPHA-GSOMA)*va + GSOMA*vd
        va0 = fma2(AG2, va0, fma2(G2, vd0, ZERO2));
        va1 = fma2(AG2, va1, fma2(G2, vd1, ZERO2));
        va2 = fma2(AG2, va2, fma2(G2, vd2, ZERO2));
        va3 = fma2(AG2, va3, fma2(G2, vd3, ZERO2));

        // spike / reset / count / APL partial (scalar)
        float part = 0.f;
        {
            float x, y;
            x = lo2(va0); y = hi2(va0);
            if ((x - VTH) > 0.f) { x = 0.f; cnt[0]++; part += aplw[0]; }
            if ((y - VTH) > 0.f) { y = 0.f; cnt[1]++; part += aplw[1]; }
            va0 = pk2(x, y);
            x = lo2(va1); y = hi2(va1);
            if ((x - VTH) > 0.f) { x = 0.f; cnt[2]++; part += aplw[2]; }
            if ((y - VTH) > 0.f) { y = 0.f; cnt[3]++; part += aplw[3]; }
            va1 = pk2(x, y);
            x = lo2(va2); y = hi2(va2);
            if ((x - VTH) > 0.f) { x = 0.f; cnt[4]++; part += aplw[4]; }
            if ((y - VTH) > 0.f) { y = 0.f; cnt[5]++; part += aplw[5]; }
            va2 = pk2(x, y);
            x = lo2(va3); y = hi2(va3);
            if ((x - VTH) > 0.f) { x = 0.f; cnt[6]++; part += aplw[6]; }
            if ((y - VTH) > 0.f) { y = 0.f; cnt[7]++; part += aplw[7]; }
            va3 = pk2(x, y);
        }
        #pragma unroll
        for (int o = 16; o; o >>= 1)
            part += __shfl_xor_sync(0xFFFFFFFFu, part, o);
        if (lane == 0) sW[t & 1][wid] = part;

        // pre-accumulate next step BEFORE barrier: vd = ALPHA*vd + rows(t+1)
        vd0 = fma2(ALPHA2, vd0, ZERO2);
        vd1 = fma2(ALPHA2, vd1, ZERO2);
        vd2 = fma2(ALPHA2, vd2, ZERO2);
        vd3 = fma2(ALPHA2, vd3, ZERO2);
        int n = sCnt[t + 1];          // sCnt[NSTEPS] == 0
        if (valid) {
            for (int i = 0; i < n; i++) {
                int off = sOff[t + 1][i];
                float4 a = __ldg((const float4*)(wbase + off));
                float4 b = __ldg((const float4*)(wbase + off + 16));
                vd0 = fma2(ONE2, pk2(a.x, a.y), vd0);
                vd1 = fma2(ONE2, pk2(a.z, a.w), vd1);
                vd2 = fma2(ONE2, pk2(b.x, b.y), vd2);
                vd3 = fma2(ONE2, pk2(b.z, b.w), vd3);
            }
        }
        __syncthreads();
    }

    // ---- compact active KCs (deterministic, ascending kc index) ----
    // Region A (k1 tiles) is dead; overlay holds sIdx/sRate/sLg.
    int act = 0;
    #pragma unroll
    for (int j = 0; j < 8; j++) if (cnt[j] > 0) act++;

    int x = act;
    #pragma unroll
    for (int dlt = 1; dlt < 32; dlt <<= 1) {
        int y = __shfl_up_sync(0xFFFFFFFFu, x, dlt);
        if (lane >= dlt) x += y;
    }
    if (lane == 31) sWTot[wid] = x;
    __syncthreads();
    int base = 0;
    #pragma unroll
    for (int w = 0; w < 8; w++) if (w < wid) base += sWTot[w];
    int pos = base + x - act;
    #pragma unroll
    for (int j = 0; j < 8; j++) {
        if (cnt[j] > 0) {
            E->sIdx[pos]  = c0 + j;
            E->sRate[pos] = (float)cnt[j] * (1.f / NSTEPS);
            pos++;
        }
    }
    __syncthreads();

    // ---- decode split over 8 warps (fixed slices -> deterministic) ----
    // lane covers odor `lane`; lanes 0-1 ALSO cover odors 32-33 (N_ODOR=34).
    int K = 0;
    #pragma unroll
    for (int w = 0; w < 8; w++) K += sWTot[w];
    int per = (K + 7) >> 3;
    int beg = wid * per;
    int end = min(K, beg + per);
    float acc0 = 0.f, acc1 = 0.f;
    for (int i = beg; i < end; i++) {
        float r = E->sRate[i];
        const float* dw = dec_w + E->sIdx[i] * N_ODOR;
        acc0 = fmaf(r, __ldg(dw + lane), acc0);
        if (lane < N_ODOR - 32)
            acc1 = fmaf(r, __ldg(dw + 32 + lane), acc1);
    }
    E->sLg[wid][lane] = acc0;
    if (lane < N_ODOR - 32) E->sLg[wid][32 + lane] = acc1;
    __syncthreads();
    if (tid < N_ODOR) {
        float su = 0.f;
        #pragma unroll
        for (int w = 0; w < 8; w++) su += E->sLg[w][tid];
        out[(size_t)row * N_ODOR + tid] = su + dec_b[tid];
    }
}

extern "C" void kernel_launch(void* const* d_in, const int* in_sizes, int n_in,
                              void* d_out, int out_size) {
    const float* or_input  = (const float*)d_in[0];   // [4096, 21]
    const float* or_gains  = (const float*)d_in[1];   // [21]
    // d_in[2] = mapping [21,42] — fixed OR i -> ORN 2i,2i+1 (folded into k1)
    const float* orn_to_pn = (const float*)d_in[3];   // [42, 42]
    const float* orn_to_ln = (const float*)d_in[4];   // [42, 56]
    const float* ln_to_pn  = (const float*)d_in[5];   // [56, 42]
    const float* pn_to_kc  = (const float*)d_in[6];   // [42, 2000]
    const float* kc_to_apl = (const float*)d_in[7];   // [2000, 1]
    const float* apl_to_kc = (const float*)d_in[8];   // [1, 2000]
    const float* dec_w     = (const float*)d_in[9];   // [2000, 34]
    const float* dec_b     = (const float*)d_in[10];  // [34]
    float* out = (float*)d_out;                       // [4096, 34]

    fused_kernel<<<BATCH, 256>>>(or_input, or_gains, orn_to_pn, orn_to_ln,
                                 ln_to_pn, pn_to_kc, kc_to_apl, apl_to_kc,
                                 dec_w, dec_b, out);
}

// round 15
// speedup vs baseline: 1.8617x; 1.8617x over previous
#include <cuda_runtime.h>
#include <cuda_bf16.h>

#define BATCH   4096
#define N_OR    21
#define N_ORN   42
#define N_LN    56
#define N_PN    42
#define N_KC    2000
#define N_ODOR  34
#define NSTEPS  20
#define ALPHA   0.9f
#define VTH     1.0f
#define GSOMA   0.3f
#define ISCALE  0.5f

// PN spike masks per (row, step): bit k = PN neuron k
__device__ unsigned long long g_masks[BATCH * NSTEPS];

// ---- packed f32x2 helpers: ONLY fma.rn.f32x2 (the verified pattern) ----
static __device__ __forceinline__ unsigned long long pk2(float lo, float hi) {
    return (unsigned long long)__float_as_uint(lo)
         | ((unsigned long long)__float_as_uint(hi) << 32);
}
static __device__ __forceinline__ float lo2(unsigned long long v) {
    return __uint_as_float((unsigned)v);
}
static __device__ __forceinline__ float hi2(unsigned long long v) {
    return __uint_as_float((unsigned)(v >> 32));
}
static __device__ __forceinline__ unsigned long long fma2(
    unsigned long long a, unsigned long long b, unsigned long long c) {
    unsigned long long r;
    asm("fma.rn.f32x2 %0,%1,%2,%3;" : "=l"(r) : "l"(a), "l"(b), "l"(c));
    return r;
}
#define ONE2   0x3F8000003F800000ull   /* { 1.0f, 1.0f} */
#define NEG12  0xBF800000BF800000ull   /* {-1.0f,-1.0f} */
#define ZERO2  0x0000000000000000ull

// spread 21-bit value to even bit positions of a 64-bit word
__device__ __forceinline__ unsigned long long spread21(unsigned x) {
    unsigned long long v = x & 0x1FFFFFu;
    v = (v | (v << 16)) & 0x0000FFFF0000FFFFull;
    v = (v | (v << 8))  & 0x00FF00FF00FF00FFull;
    v = (v | (v << 4))  & 0x0F0F0F0F0F0F0F0Full;
    v = (v | (v << 2))  & 0x3333333333333333ull;
    v = (v | (v << 1))  & 0x5555555555555555ull;
    return v;
}

// ---------------------------------------------------------------------------
// Kernel 1: ORN/LN/PN cascade. One warp per row. ORN 2i,2i+1 share drive ->
// one state per OR, weight rows pair-summed. Shared tiles stored as packed
// u64 (float2) and all accumulate loops use fma.rn.f32x2, preserving the
// exact per-half summation order of the proven round-12 kernel
// (fma2(1,w,acc) == acc+w; complement path fma2(-1,w,acc) == acc-w).
// ---------------------------------------------------------------------------
__global__ __launch_bounds__(256) void k1_masks(
    const float* __restrict__ or_input, const float* __restrict__ or_gains,
    const float* __restrict__ orn_to_pn, const float* __restrict__ orn_to_ln,
    const float* __restrict__ ln_to_pn)
{
    __shared__ unsigned long long sOLp[N_OR][32];  // pair-summed orn_to_ln (28 used)
    __shared__ unsigned long long sOPp[N_OR][32];  // pair-summed orn_to_pn (21 used)
    __shared__ unsigned long long sLP[N_LN][32];   // ln_to_pn rows (21 used)
    __shared__ unsigned long long sLPtot[32];      // column sums of ln_to_pn
    __shared__ float sSg[N_OR];

    int tid = threadIdx.x;
    for (int i = tid; i < N_OR * 32; i += 256) {
        int p = i >> 5, c = i & 31;
        float ax = 0.f, ay = 0.f, bx = 0.f, by = 0.f;
        if (c < 28) {
            float2 r0 = ((const float2*)(orn_to_ln + (2 * p)     * N_LN))[c];
            float2 r1 = ((const float2*)(orn_to_ln + (2 * p + 1) * N_LN))[c];
            ax = r0.x + r1.x; ay = r0.y + r1.y;
        }
        if (c < 21) {
            float2 r0 = ((const float2*)(orn_to_pn + (2 * p)     * N_PN))[c];
            float2 r1 = ((const float2*)(orn_to_pn + (2 * p + 1) * N_PN))[c];
            bx = r0.x + r1.x; by = r0.y + r1.y;
        }
        sOLp[p][c] = pk2(ax, ay);
        sOPp[p][c] = pk2(bx, by);
    }
    for (int i = tid; i < N_LN * 32; i += 256) {
        int r = i >> 5, c = i & 31;
        float wx = 0.f, wy = 0.f;
        if (c < 21) {
            float2 w = ((const float2*)(ln_to_pn + r * N_PN))[c];
            wx = w.x; wy = w.y;
        }
        sLP[r][c] = pk2(wx, wy);
    }
    if (tid < N_OR) sSg[tid] = log1pf(expf(or_gains[tid]));  // softplus
    __syncthreads();
    if (tid < 32) {
        float sx = 0.f, sy = 0.f;
        for (int r = 0; r < N_LN; r++) {
            sx += lo2(sLP[r][tid]); sy += hi2(sLP[r][tid]);
        }
        sLPtot[tid] = pk2(sx, sy);
    }
    __syncthreads();

    int warp = tid >> 5, lane = tid & 31;
    int row = (blockIdx.x << 3) + warp;

    float d = (lane < N_OR)
            ? or_input[row * N_OR + lane] * sSg[lane] * ISCALE : 0.f;

    float vO = 0.f;
    unsigned long long vL2 = ZERO2, vP2 = ZERO2;
    unsigned long long* mout = g_masks + (size_t)row * NSTEPS;

    for (int t = 0; t < NSTEPS; t++) {
        // ORN LIF (one state per OR pair)
        vO = ALPHA * vO + d;
        bool sO = (vO - VTH) > 0.f;
        unsigned bO = __ballot_sync(0xFFFFFFFFu, sO) & 0x1FFFFFu;
        if (sO) vO = 0.f;

        // merged LN drive + PN excitation over OR-pair spikes (packed fma)
        unsigned long long aL2 = ZERO2, eE2 = ZERO2;
        unsigned m = bO;
        while (m) {
            int p = __ffs(m) - 1; m &= m - 1;
            aL2 = fma2(ONE2, sOLp[p][lane], aL2);
            eE2 = fma2(ONE2, sOPp[p][lane], eE2);
        }

        // LN LIF: vL = ALPHA*vL + aL (single-rounding FMA per half)
        vL2 = fma2(pk2(ALPHA, ALPHA), vL2, aL2);
        {
            float x = lo2(vL2), y = hi2(vL2);
            bool sx = (x - VTH) > 0.f, sy = (y - VTH) > 0.f;
            unsigned bLx = __ballot_sync(0xFFFFFFFFu, sx) & 0x0FFFFFFFu;
            unsigned bLy = __ballot_sync(0xFFFFFFFFu, sy) & 0x0FFFFFFFu;
            vL2 = pk2(sx ? 0.f : x, sy ? 0.f : y);

            // LN->PN inhibition: direct or complement (uniform branch)
            unsigned long long iI2;
            int nb = __popc(bLx) + __popc(bLy);
            if (nb > 28) {
                iI2 = sLPtot[lane];
                m = ~bLx & 0x0FFFFFFFu;
                while (m) {
                    int p = __ffs(m) - 1; m &= m - 1;
                    iI2 = fma2(NEG12, sLP[2 * p][lane], iI2);
                }
                m = ~bLy & 0x0FFFFFFFu;
                while (m) {
                    int p = __ffs(m) - 1; m &= m - 1;
                    iI2 = fma2(NEG12, sLP[2 * p + 1][lane], iI2);
                }
            } else {
                iI2 = ZERO2;
                m = bLx;
                while (m) {
                    int p = __ffs(m) - 1; m &= m - 1;
                    iI2 = fma2(ONE2, sLP[2 * p][lane], iI2);
                }
                m = bLy;
                while (m) {
                    int p = __ffs(m) - 1; m &= m - 1;
                    iI2 = fma2(ONE2, sLP[2 * p + 1][lane], iI2);
                }
            }

            // PN LIF: vP = (ALPHA*vP + eE) - iI
            vP2 = fma2(pk2(ALPHA, ALPHA), vP2, eE2);
            vP2 = fma2(NEG12, iI2, vP2);
        }
        {
            float x = lo2(vP2), y = hi2(vP2);
            bool sx = (x - VTH) > 0.f, sy = (y - VTH) > 0.f;
            unsigned bPx = __ballot_sync(0xFFFFFFFFu, sx) & 0x1FFFFFu;
            unsigned bPy = __ballot_sync(0xFFFFFFFFu, sy) & 0x1FFFFFu;
            vP2 = pk2(sx ? 0.f : x, sy ? 0.f : y);

            if (lane == 0)
                mout[t] = spread21(bPx) | (spread21(bPy) << 1);
        }
    }
}

// ---------------------------------------------------------------------------
// Kernel 2: KC dynamics + APL + decode — VERBATIM round-12 proven version.
// One CTA/row, 8 KC cols/thread, packed f32x2 state, float4 weight loads,
// prefetch-before-barrier, one barrier/step, warp-sliced decode (34 cols).
// ---------------------------------------------------------------------------
__global__ __launch_bounds__(256, 4) void k2_kc(
    const float* __restrict__ pn_to_kc, const float* __restrict__ kc_to_apl,
    const float* __restrict__ apl_to_kc, const float* __restrict__ dec_w,
    const float* __restrict__ dec_b, float* __restrict__ out)
{
    __shared__ int   sCnt[NSTEPS + 1];
    __shared__ int   sOff[NSTEPS + 1][N_PN];
    __shared__ float sW[2][8];
    __shared__ int   sT0;
    __shared__ int   sWTot[8];
    __shared__ int   sIdx[2048];
    __shared__ float sRate[2048];
    __shared__ float sLg[8][N_ODOR];

    int tid = threadIdx.x;
    int lane = tid & 31, wid = tid >> 5;
    int row = blockIdx.x;

    if (tid < 8) { sW[0][tid] = 0.f; sW[1][tid] = 0.f; }
    if (tid < 32) {
        int n = 0;
        if (tid < NSTEPS) {
            unsigned long long m = g_masks[(size_t)row * NSTEPS + tid];
            while (m) {
                int k = __ffsll((long long)m) - 1; m &= m - 1;
                sOff[tid][n++] = k * (N_KC * 4);   // byte offset of weight row
            }
            sCnt[tid] = n;
        }
        if (tid == NSTEPS) sCnt[NSTEPS] = 0;
        unsigned nz = __ballot_sync(0xFFFFFFFFu, n > 0);
        if (tid == 0) sT0 = nz ? (__ffs(nz) - 1) : NSTEPS;
    }
    __syncthreads();

    int t0 = sT0;
    if (t0 >= NSTEPS) {   // no PN spikes ever -> logits = dec_b
        if (tid < N_ODOR) out[(size_t)row * N_ODOR + tid] = dec_b[tid];
        return;
    }

    int c0 = tid * 8;
    bool valid = (c0 < N_KC);
    const char* wbase = (const char*)(pn_to_kc + (valid ? c0 : 0));
    const float* aplkp = apl_to_kc + (valid ? c0 : 0);
    const float* aplwp = kc_to_apl + (valid ? c0 : 0);

    unsigned long long aplk0 = 0, aplk1 = 0, aplk2 = 0, aplk3 = 0;
    float aplw[8];
    if (valid) {
        aplk0 = pk2(aplkp[0], aplkp[1]);
        aplk1 = pk2(aplkp[2], aplkp[3]);
        aplk2 = pk2(aplkp[4], aplkp[5]);
        aplk3 = pk2(aplkp[6], aplkp[7]);
        #pragma unroll
        for (int j = 0; j < 8; j++) aplw[j] = aplwp[j];
    } else {
        #pragma unroll
        for (int j = 0; j < 8; j++) aplw[j] = 0.f;
    }

    unsigned long long vd0 = 0, vd1 = 0, vd2 = 0, vd3 = 0;
    unsigned long long va0 = 0, va1 = 0, va2 = 0, va3 = 0;
    int cnt[8];
    #pragma unroll
    for (int j = 0; j < 8; j++) cnt[j] = 0;

    const unsigned long long ALPHA2 = pk2(ALPHA, ALPHA);
    const unsigned long long AG2    = pk2(ALPHA - GSOMA, ALPHA - GSOMA);
    const unsigned long long G2     = pk2(GSOMA, GSOMA);

    // prefetch step t0 rows into vd (state is exactly zero before t0)
    if (valid) {
        int n = sCnt[t0];
        for (int i = 0; i < n; i++) {
            int off = sOff[t0][i];
            float4 a = __ldg((const float4*)(wbase + off));
            float4 b = __ldg((const float4*)(wbase + off + 16));
            vd0 = fma2(ONE2, pk2(a.x, a.y), vd0);
            vd1 = fma2(ONE2, pk2(a.z, a.w), vd1);
            vd2 = fma2(ONE2, pk2(b.x, b.y), vd2);
            vd3 = fma2(ONE2, pk2(b.z, b.w), vd3);
        }
    }

    for (int t = t0; t < NSTEPS; t++) {
        // APL from previous step (buffer (t+1)&1, zero at t0): fixed-order sum
        const float* wprev = sW[(t + 1) & 1];
        float apl = ((((((wprev[0] + wprev[1]) + wprev[2]) + wprev[3])
                     + wprev[4]) + wprev[5]) + wprev[6]) + wprev[7];

        // vd -= apl * aplk  (apl==0 is an exact no-op)
        unsigned long long napl2 = pk2(-apl, -apl);
        vd0 = fma2(napl2, aplk0, vd0);
        vd1 = fma2(napl2, aplk1, vd1);
        vd2 = fma2(napl2, aplk2, vd2);
        vd3 = fma2(napl2, aplk3, vd3);

        // axon compartment: va = (ALPHA-GSOMA)*va + GSOMA*vd
        va0 = fma2(AG2, va0, fma2(G2, vd0, ZERO2));
        va1 = fma2(AG2, va1, fma2(G2, vd1, ZERO2));
        va2 = fma2(AG2, va2, fma2(G2, vd2, ZERO2));
        va3 = fma2(AG2, va3, fma2(G2, vd3, ZERO2));

        // spike / reset / count / APL partial (scalar)
        float part = 0.f;
        {
            float x, y;
            x = lo2(va0); y = hi2(va0);
            if ((x - VTH) > 0.f) { x = 0.f; cnt[0]++; part += aplw[0]; }
            if ((y - VTH) > 0.f) { y = 0.f; cnt[1]++; part += aplw[1]; }
            va0 = pk2(x, y);
            x = lo2(va1); y = hi2(va1);
            if ((x - VTH) > 0.f) { x = 0.f; cnt[2]++; part += aplw[2]; }
            if ((y - VTH) > 0.f) { y = 0.f; cnt[3]++; part += aplw[3]; }
            va1 = pk2(x, y);
            x = lo2(va2); y = hi2(va2);
            if ((x - VTH) > 0.f) { x = 0.f; cnt[4]++; part += aplw[4]; }
            if ((y - VTH) > 0.f) { y = 0.f; cnt[5]++; part += aplw[5]; }
            va2 = pk2(x, y);
            x = lo2(va3); y = hi2(va3);
            if ((x - VTH) > 0.f) { x = 0.f; cnt[6]++; part += aplw[6]; }
            if ((y - VTH) > 0.f) { y = 0.f; cnt[7]++; part += aplw[7]; }
            va3 = pk2(x, y);
        }
        #pragma unroll
        for (int o = 16; o; o >>= 1)
            part += __shfl_xor_sync(0xFFFFFFFFu, part, o);
        if (lane == 0) sW[t & 1][wid] = part;

        // pre-accumulate next step BEFORE barrier: vd = ALPHA*vd + rows(t+1)
        vd0 = fma2(ALPHA2, vd0, ZERO2);
        vd1 = fma2(ALPHA2, vd1, ZERO2);
        vd2 = fma2(ALPHA2, vd2, ZERO2);
        vd3 = fma2(ALPHA2, vd3, ZERO2);
        int n = sCnt[t + 1];          // sCnt[NSTEPS] == 0
        if (valid) {
            for (int i = 0; i < n; i++) {
                int off = sOff[t + 1][i];
                float4 a = __ldg((const float4*)(wbase + off));
                float4 b = __ldg((const float4*)(wbase + off + 16));
                vd0 = fma2(ONE2, pk2(a.x, a.y), vd0);
                vd1 = fma2(ONE2, pk2(a.z, a.w), vd1);
                vd2 = fma2(ONE2, pk2(b.x, b.y), vd2);
                vd3 = fma2(ONE2, pk2(b.z, b.w), vd3);
            }
        }
        __syncthreads();
    }

    // ---- compact active KCs (deterministic, ascending kc index) ----
    int act = 0;
    #pragma unroll
    for (int j = 0; j < 8; j++) if (cnt[j] > 0) act++;

    int x = act;
    #pragma unroll
    for (int dlt = 1; dlt < 32; dlt <<= 1) {
        int y = __shfl_up_sync(0xFFFFFFFFu, x, dlt);
        if (lane >= dlt) x += y;
    }
    if (lane == 31) sWTot[wid] = x;
    __syncthreads();
    int base = 0;
    #pragma unroll
    for (int w = 0; w < 8; w++) if (w < wid) base += sWTot[w];
    int pos = base + x - act;
    #pragma unroll
    for (int j = 0; j < 8; j++) {
        if (cnt[j] > 0) {
            sIdx[pos]  = c0 + j;
            sRate[pos] = (float)cnt[j] * (1.f / NSTEPS);
            pos++;
        }
    }
    __syncthreads();

    // ---- decode split over 8 warps (fixed slices -> deterministic) ----
    // lane covers odor `lane`; lanes 0-1 ALSO cover odors 32-33 (N_ODOR=34).
    int K = 0;
    #pragma unroll
    for (int w = 0; w < 8; w++) K += sWTot[w];
    int per = (K + 7) >> 3;
    int beg = wid * per;
    int end = min(K, beg + per);
    float acc0 = 0.f, acc1 = 0.f;
    for (int i = beg; i < end; i++) {
        float r = sRate[i];
        const float* dw = dec_w + sIdx[i] * N_ODOR;
        acc0 = fmaf(r, __ldg(dw + lane), acc0);
        if (lane < N_ODOR - 32)
            acc1 = fmaf(r, __ldg(dw + 32 + lane), acc1);
    }
    sLg[wid][lane] = acc0;
    if (lane < N_ODOR - 32) sLg[wid][32 + lane] = acc1;
    __syncthreads();
    if (tid < N_ODOR) {
        float su = 0.f;
        #pragma unroll
        for (int w = 0; w < 8; w++) su += sLg[w][tid];
        out[(size_t)row * N_ODOR + tid] = su + dec_b[tid];
    }
}

extern "C" void kernel_launch(void* const* d_in, const int* in_sizes, int n_in,
                              void* d_out, int out_size) {
    const float* or_input  = (const float*)d_in[0];   // [4096, 21]
    const float* or_gains  = (const float*)d_in[1];   // [21]
    // d_in[2] = mapping [21,42] — fixed OR i -> ORN 2i,2i+1 (folded into k1)
    const float* orn_to_pn = (const float*)d_in[3];   // [42, 42]
    const float* orn_to_ln = (const float*)d_in[4];   // [42, 56]
    const float* ln_to_pn  = (const float*)d_in[5];   // [56, 42]
    const float* pn_to_kc  = (const float*)d_in[6];   // [42, 2000]
    const float* kc_to_apl = (const float*)d_in[7];   // [2000, 1]
    const float* apl_to_kc = (const float*)d_in[8];   // [1, 2000]
    const float* dec_w     = (const float*)d_in[9];   // [2000, 34]
    const float* dec_b     = (const float*)d_in[10];  // [34]
    float* out = (float*)d_out;                       // [4096, 34]

    k1_masks<<<BATCH / 8, 256>>>(or_input, or_gains,
                                 orn_to_pn, orn_to_ln, ln_to_pn);
    k2_kc<<<BATCH, 256>>>(pn_to_kc, kc_to_apl, apl_to_kc, dec_w, dec_b, out);
}